// round 1
// baseline (speedup 1.0000x reference)
#include <cuda_runtime.h>
#include <cuda_bf16.h>

#define D      512   // hidden dim
#define KC     512   // n clusters
#define BM      64   // rows per CTA
#define BK      16   // k-slice
#define NTHREADS 512

// ||c||^2 scratch (allocation-free per harness rules)
__device__ float g_c2[KC];

// ---------------------------------------------------------------------------
// Precompute ||c||^2 for each cluster. One block per cluster.
// ---------------------------------------------------------------------------
__global__ void c2_kernel(const float* __restrict__ centers) {
    const int c   = blockIdx.x;
    const int tid = threadIdx.x;                 // 128 threads
    const float4* row = reinterpret_cast<const float4*>(centers + (size_t)c * D);
    float s = 0.f;
    for (int i = tid; i < D / 4; i += 128) {
        float4 v = row[i];
        s += v.x * v.x + v.y * v.y + v.z * v.z + v.w * v.w;
    }
    #pragma unroll
    for (int o = 16; o > 0; o >>= 1) s += __shfl_xor_sync(0xffffffffu, s, o);
    __shared__ float ws[4];
    if ((tid & 31) == 0) ws[tid >> 5] = s;
    __syncthreads();
    if (tid == 0) g_c2[c] = ws[0] + ws[1] + ws[2] + ws[3];
}

// ---------------------------------------------------------------------------
// Fused: dist2 GEMM + student-t + row-normalize.
// CTA: BM=64 rows x all 512 clusters. 512 threads.
// Thread (ty = tid/32 in [0,16), tx = lane): rows ty*4+i, cols tx+32*j.
// A warp covers 4 complete rows -> rowsum via shfl only.
// ---------------------------------------------------------------------------
__global__ __launch_bounds__(NTHREADS, 1)
void qsoft_kernel(const float* __restrict__ x,
                  const float* __restrict__ centers,
                  float* __restrict__ out, int N) {
    __shared__ float As[BM][BK + 1];   // +1 pad: conflict-free
    __shared__ float Bs[KC][BK + 1];

    const int tid = threadIdx.x;
    const int tx  = tid & 31;
    const int ty  = tid >> 5;          // 0..15
    const int rowBase = blockIdx.x * BM;

    float acc[4][16];
    #pragma unroll
    for (int i = 0; i < 4; i++)
        #pragma unroll
        for (int j = 0; j < 16; j++) acc[i][j] = 0.f;
    float xs[4] = {0.f, 0.f, 0.f, 0.f};

    for (int k0 = 0; k0 < D; k0 += BK) {
        // ---- load A tile: 64 rows x 16 = 256 float4, threads 0..255 ----
        if (tid < 256) {
            int r = tid >> 2;          // row in tile
            int q = tid & 3;           // float4 index within BK
            float4 v = *reinterpret_cast<const float4*>(
                x + (size_t)(rowBase + r) * D + k0 + q * 4);
            As[r][q * 4 + 0] = v.x;
            As[r][q * 4 + 1] = v.y;
            As[r][q * 4 + 2] = v.z;
            As[r][q * 4 + 3] = v.w;
        }
        // ---- load B tile: 512 rows x 16 = 2048 float4, 4 per thread ----
        #pragma unroll
        for (int it = 0; it < 4; it++) {
            int idx = tid + it * NTHREADS;
            int r = idx >> 2;
            int q = idx & 3;
            float4 v = *reinterpret_cast<const float4*>(
                centers + (size_t)r * D + k0 + q * 4);
            Bs[r][q * 4 + 0] = v.x;
            Bs[r][q * 4 + 1] = v.y;
            Bs[r][q * 4 + 2] = v.z;
            Bs[r][q * 4 + 3] = v.w;
        }
        __syncthreads();

        #pragma unroll
        for (int kk = 0; kk < BK; kk++) {
            float a[4], b[16];
            #pragma unroll
            for (int i = 0; i < 4; i++) a[i] = As[ty * 4 + i][kk];   // broadcast
            #pragma unroll
            for (int j = 0; j < 16; j++) b[j] = Bs[tx + 32 * j][kk]; // stride-17
            #pragma unroll
            for (int i = 0; i < 4; i++) xs[i] = fmaf(a[i], a[i], xs[i]);
            #pragma unroll
            for (int i = 0; i < 4; i++)
                #pragma unroll
                for (int j = 0; j < 16; j++)
                    acc[i][j] = fmaf(a[i], b[j], acc[i][j]);
        }
        __syncthreads();
    }

    // ---- epilogue: dist2 -> q -> row-normalize -> store ----
    float cs[16];
    #pragma unroll
    for (int j = 0; j < 16; j++) cs[j] = g_c2[tx + 32 * j];

    #pragma unroll
    for (int i = 0; i < 4; i++) {
        float qv[16];
        float rs = 0.f;
        #pragma unroll
        for (int j = 0; j < 16; j++) {
            float d2 = xs[i] + cs[j] - 2.f * acc[i][j];
            d2 = fmaxf(d2, 0.f);
            float qq = 1.f / (1.f + d2);   // ALPHA=1, exponent (1+1)/2 = 1
            qv[j] = qq;
            rs += qq;
        }
        #pragma unroll
        for (int o = 16; o > 0; o >>= 1)
            rs += __shfl_xor_sync(0xffffffffu, rs, o);   // full-row sum (warp owns row)
        float inv = 1.f / rs;
        int row = rowBase + ty * 4 + i;
        if (row < N) {
            float* orow = out + (size_t)row * KC;
            #pragma unroll
            for (int j = 0; j < 16; j++)
                orow[tx + 32 * j] = qv[j] * inv;          // coalesced STG.32
        }
    }
}

// ---------------------------------------------------------------------------
extern "C" void kernel_launch(void* const* d_in, const int* in_sizes, int n_in,
                              void* d_out, int out_size) {
    const float* x       = (const float*)d_in[0];
    const float* centers = (const float*)d_in[1];
    float*       out     = (float*)d_out;
    const int N = in_sizes[0] / D;     // 131072

    c2_kernel<<<KC, 128>>>(centers);
    qsoft_kernel<<<(N + BM - 1) / BM, NTHREADS>>>(x, centers, out, N);
}

// round 5
// speedup vs baseline: 6.0366x; 6.0366x over previous
#include <cuda_runtime.h>
#include <cuda_bf16.h>
#include <cstdint>

#define DHID   512
#define KC     512
#define BM     64
#define BK     64          // K elems per chunk = 128 bytes bf16
#define NCH    (DHID/BK)   // 8 chunks
#define NT     256

#define A_STAGE (BM * 128)             // 8 KB
#define B_STAGE (KC * 128)             // 64 KB
#define DYN_SMEM (2*(A_STAGE + B_STAGE) + 1024)

__device__ __nv_bfloat16 g_wbf[KC * DHID];   // centers bf16, [n][k] row-major
__device__ float         g_c2[KC];

// ---------------------------------------------------------------------------
__device__ __forceinline__ uint32_t smem_u32(const void* p) {
    uint32_t a;
    asm("{ .reg .u64 t; cvta.to.shared.u64 t, %1; cvt.u32.u64 %0, t; }" : "=r"(a) : "l"(p));
    return a;
}
__device__ __forceinline__ uint32_t pack_bf16(float lo, float hi) {
    uint32_t r;
    asm("cvt.rn.bf16x2.f32 %0, %1, %2;" : "=r"(r) : "f"(hi), "f"(lo));
    return r;
}
#define SWZ128(o) ((o) ^ (((o) >> 3) & 0x70))

__device__ __forceinline__ void cp_async16(uint32_t dst, const void* src) {
    asm volatile("cp.async.cg.shared.global [%0], [%1], 16;\n" :: "r"(dst), "l"(src) : "memory");
}
#define CP_COMMIT() asm volatile("cp.async.commit_group;\n" ::: "memory")
#define CP_WAIT0()  asm volatile("cp.async.wait_group 0;\n" ::: "memory")

#define LDSM4(r, a) \
    asm volatile("ldmatrix.sync.aligned.m8n8.x4.shared.b16 {%0,%1,%2,%3}, [%4];" \
                 : "=r"((r)[0]), "=r"((r)[1]), "=r"((r)[2]), "=r"((r)[3]) : "r"(a))

#define MMA16816(d, a, b0, b1) \
    asm volatile("mma.sync.aligned.m16n8k16.row.col.f32.bf16.bf16.f32 " \
                 "{%0,%1,%2,%3}, {%4,%5,%6,%7}, {%8,%9}, {%0,%1,%2,%3};" \
                 : "+f"((d)[0]), "+f"((d)[1]), "+f"((d)[2]), "+f"((d)[3]) \
                 : "r"((a)[0]), "r"((a)[1]), "r"((a)[2]), "r"((a)[3]), \
                   "r"(b0), "r"(b1))

// ---------------------------------------------------------------------------
// Prep: centers fp32 -> bf16 + ||c||^2. One block per cluster row.
// ---------------------------------------------------------------------------
__global__ void prep_kernel(const float* __restrict__ centers) {
    const int c = blockIdx.x, t = threadIdx.x;       // 256 threads
    const float2* row = reinterpret_cast<const float2*>(centers + (size_t)c * DHID);
    float2 v = row[t];
    reinterpret_cast<uint32_t*>(g_wbf + (size_t)c * DHID)[t] = pack_bf16(v.x, v.y);
    float s = v.x * v.x + v.y * v.y;
    #pragma unroll
    for (int o = 16; o > 0; o >>= 1) s += __shfl_xor_sync(0xffffffffu, s, o);
    __shared__ float ws[8];
    if ((t & 31) == 0) ws[t >> 5] = s;
    __syncthreads();
    if (t == 0) {
        float tot = 0.f;
        #pragma unroll
        for (int i = 0; i < 8; i++) tot += ws[i];
        g_c2[c] = tot;
    }
}

// ---------------------------------------------------------------------------
// Main fused kernel: 64 rows x 512 clusters per CTA, 8 warps.
// ---------------------------------------------------------------------------
extern __shared__ char dynsmem[];

__global__ __launch_bounds__(NT, 1)
void qsoft_mma_kernel(const float* __restrict__ x, float* __restrict__ out) {
    __shared__ float xs_sm[BM];
    __shared__ float c2s[KC];
    __shared__ float rs_sm[BM][8];
    __shared__ float inv_sm[BM];

    const int tid  = threadIdx.x;
    const int wid  = tid >> 5;
    const int lane = tid & 31;
    const int rowBase = blockIdx.x * BM;

    const uint32_t sbase = (smem_u32(dynsmem) + 1023u) & ~1023u;
    const uint32_t Abuf[2] = { sbase,              sbase + A_STAGE };
    const uint32_t Bbuf[2] = { sbase + 2*A_STAGE,  sbase + 2*A_STAGE + B_STAGE };

    // per-thread A-load mapping: row = tid/4, 16 floats at col (tid%4)*16
    const int arow = tid >> 2;
    const int acol = (tid & 3) * 16;

    float acc[4][8][4];
    #pragma unroll
    for (int mi = 0; mi < 4; mi++)
        #pragma unroll
        for (int ni = 0; ni < 8; ni++)
            #pragma unroll
            for (int e = 0; e < 4; e++) acc[mi][ni][e] = 0.f;

    float sq = 0.f;
    float4 f[4];

    // ldmatrix lane addressing (within-tile offsets)
    const int a_r  = ((lane >> 3) & 1) * 8 + (lane & 7);   // A: row offset in m16
    const int a_kb = ((lane >> 4) & 1) * 16;               // A: k-byte offset
    const int b_r  = ((lane >> 4) & 1) * 8 + (lane & 7);   // B: row offset in n16
    const int b_kb = ((lane >> 3) & 1) * 16;               // B: k-byte offset

    // ---------------- loaders ----------------
    auto lda = [&](int c) {
        const float4* src = reinterpret_cast<const float4*>(
            x + (size_t)(rowBase + arow) * DHID + c * BK + acol);
        #pragma unroll
        for (int i = 0; i < 4; i++) f[i] = src[i];
    };
    auto sta = [&](int s) {
        #pragma unroll
        for (int i = 0; i < 4; i++)
            sq += f[i].x*f[i].x + f[i].y*f[i].y + f[i].z*f[i].z + f[i].w*f[i].w;
        #pragma unroll
        for (int h = 0; h < 2; h++) {
            uint32_t p0 = pack_bf16(f[2*h].x,   f[2*h].y);
            uint32_t p1 = pack_bf16(f[2*h].z,   f[2*h].w);
            uint32_t p2 = pack_bf16(f[2*h+1].x, f[2*h+1].y);
            uint32_t p3 = pack_bf16(f[2*h+1].z, f[2*h+1].w);
            uint32_t off = (uint32_t)arow * 128u + (uint32_t)(tid & 3) * 32u + h * 16u;
            asm volatile("st.shared.v4.b32 [%0], {%1,%2,%3,%4};"
                         :: "r"(Abuf[s] + SWZ128(off)),
                            "r"(p0), "r"(p1), "r"(p2), "r"(p3) : "memory");
        }
    };
    auto ldb = [&](int c, int s) {
        #pragma unroll
        for (int k = 0; k < 16; k++) {
            int idx = tid + k * NT;          // 0..4095 (16B chunks)
            int n = idx >> 3, i = idx & 7;
            const char* src = reinterpret_cast<const char*>(g_wbf)
                            + (size_t)n * (DHID * 2) + c * 128 + i * 16;
            uint32_t off = (uint32_t)n * 128u + (uint32_t)i * 16u;
            cp_async16(Bbuf[s] + SWZ128(off), src);
        }
    };

    // ---------------- compute one K-chunk ----------------
    auto compute = [&](int s) {
        const uint32_t Ab = Abuf[s], Bb = Bbuf[s];
        #pragma unroll
        for (int ks = 0; ks < 4; ks++) {
            uint32_t b[4][4];
            #pragma unroll
            for (int j = 0; j < 4; j++) {
                uint32_t off = (uint32_t)(wid * 64 + j * 16 + b_r) * 128u
                             + (uint32_t)(ks * 32 + b_kb);
                LDSM4(b[j], Bb + SWZ128(off));
            }
            #pragma unroll
            for (int mi = 0; mi < 4; mi++) {
                uint32_t a[4];
                uint32_t off = (uint32_t)(mi * 16 + a_r) * 128u
                             + (uint32_t)(ks * 32 + a_kb);
                LDSM4(a, Ab + SWZ128(off));
                #pragma unroll
                for (int j = 0; j < 4; j++) {
                    MMA16816(acc[mi][2*j],   a, b[j][0], b[j][1]);
                    MMA16816(acc[mi][2*j+1], a, b[j][2], b[j][3]);
                }
            }
        }
    };

    // ---------------- pipeline ----------------
    lda(0);
    ldb(0, 0); CP_COMMIT();
    sta(0);
    CP_WAIT0(); __syncthreads();

    for (int c = 0; c < NCH; c++) {
        const int s = c & 1;
        if (c + 1 < NCH) { lda(c + 1); ldb(c + 1, s ^ 1); CP_COMMIT(); }
        compute(s);
        if (c + 1 < NCH) { sta(s ^ 1); CP_WAIT0(); }
        __syncthreads();
    }

    // ---------------- epilogue ----------------
    sq += __shfl_xor_sync(0xffffffffu, sq, 1);
    sq += __shfl_xor_sync(0xffffffffu, sq, 2);
    if ((tid & 3) == 0) xs_sm[arow] = sq;
    for (int i = tid; i < KC; i += NT) c2s[i] = g_c2[i];
    __syncthreads();

    const int qrow = lane >> 2;            // 0..7
    const int wcol = wid * 64 + (lane & 3) * 2;

    float rsum[8];
    #pragma unroll
    for (int i = 0; i < 8; i++) rsum[i] = 0.f;

    #pragma unroll
    for (int mi = 0; mi < 4; mi++) {
        const float x20 = xs_sm[mi * 16 + qrow];
        const float x21 = xs_sm[mi * 16 + qrow + 8];
        #pragma unroll
        for (int ni = 0; ni < 8; ni++) {
            const float cc0 = c2s[wcol + ni * 8];
            const float cc1 = c2s[wcol + ni * 8 + 1];
            float q0 = __fdividef(1.f, 1.f + fmaxf(fmaf(-2.f, acc[mi][ni][0], x20 + cc0), 0.f));
            float q1 = __fdividef(1.f, 1.f + fmaxf(fmaf(-2.f, acc[mi][ni][1], x20 + cc1), 0.f));
            float q2 = __fdividef(1.f, 1.f + fmaxf(fmaf(-2.f, acc[mi][ni][2], x21 + cc0), 0.f));
            float q3 = __fdividef(1.f, 1.f + fmaxf(fmaf(-2.f, acc[mi][ni][3], x21 + cc1), 0.f));
            acc[mi][ni][0] = q0; acc[mi][ni][1] = q1;
            acc[mi][ni][2] = q2; acc[mi][ni][3] = q3;
            rsum[2*mi]   += q0 + q1;
            rsum[2*mi+1] += q2 + q3;
        }
    }
    #pragma unroll
    for (int i = 0; i < 8; i++) {
        float v = rsum[i];
        v += __shfl_xor_sync(0xffffffffu, v, 1);
        v += __shfl_xor_sync(0xffffffffu, v, 2);
        rsum[i] = v;
    }
    if ((lane & 3) == 0) {
        #pragma unroll
        for (int mi = 0; mi < 4; mi++) {
            rs_sm[mi * 16 + qrow][wid]     = rsum[2*mi];
            rs_sm[mi * 16 + qrow + 8][wid] = rsum[2*mi+1];
        }
    }
    __syncthreads();
    if (tid < BM) {
        float t = 0.f;
        #pragma unroll
        for (int w = 0; w < 8; w++) t += rs_sm[tid][w];
        inv_sm[tid] = __fdividef(1.f, t);
    }
    __syncthreads();

    #pragma unroll
    for (int mi = 0; mi < 4; mi++) {
        const int r0 = mi * 16 + qrow, r1 = r0 + 8;
        const float inv0 = inv_sm[r0], inv1 = inv_sm[r1];
        float* o0 = out + (size_t)(rowBase + r0) * KC + wcol;
        float* o1 = out + (size_t)(rowBase + r1) * KC + wcol;
        #pragma unroll
        for (int ni = 0; ni < 8; ni++) {
            *reinterpret_cast<float2*>(o0 + ni * 8) =
                make_float2(acc[mi][ni][0] * inv0, acc[mi][ni][1] * inv0);
            *reinterpret_cast<float2*>(o1 + ni * 8) =
                make_float2(acc[mi][ni][2] * inv1, acc[mi][ni][3] * inv1);
        }
    }
}

// ---------------------------------------------------------------------------
extern "C" void kernel_launch(void* const* d_in, const int* in_sizes, int n_in,
                              void* d_out, int out_size) {
    const float* x       = (const float*)d_in[0];
    const float* centers = (const float*)d_in[1];
    float*       out     = (float*)d_out;
    const int N = in_sizes[0] / DHID;   // 131072

    cudaFuncSetAttribute(qsoft_mma_kernel,
                         cudaFuncAttributeMaxDynamicSharedMemorySize, DYN_SMEM);

    prep_kernel<<<KC, 256>>>(centers);
    qsoft_mma_kernel<<<N / BM, NT, DYN_SMEM>>>(x, out);
}

// round 6
// speedup vs baseline: 7.0505x; 1.1680x over previous
#include <cuda_runtime.h>
#include <cuda_bf16.h>
#include <cstdint>

#define DHID   512
#define KC     512
#define BM     64
#define BK     64          // K elems per chunk = 128 bytes bf16
#define NCH    (DHID/BK)   // 8 chunks
#define NT     512         // 16 warps

#define A_STAGE (BM * 128)             // 8 KB
#define B_STAGE (KC * 128)             // 64 KB
#define DYN_SMEM (2*(A_STAGE + B_STAGE) + 1024)

__device__ __nv_bfloat16 g_wbf[KC * DHID];   // centers bf16, [n][k] row-major
__device__ float         g_c2[KC];

// ---------------------------------------------------------------------------
__device__ __forceinline__ uint32_t smem_u32(const void* p) {
    uint32_t a;
    asm("{ .reg .u64 t; cvta.to.shared.u64 t, %1; cvt.u32.u64 %0, t; }" : "=r"(a) : "l"(p));
    return a;
}
__device__ __forceinline__ uint32_t pack_bf16(float lo, float hi) {
    uint32_t r;
    asm("cvt.rn.bf16x2.f32 %0, %1, %2;" : "=r"(r) : "f"(hi), "f"(lo));
    return r;
}
#define SWZ128(o) ((o) ^ (((o) >> 3) & 0x70))

__device__ __forceinline__ void cp_async16(uint32_t dst, const void* src) {
    asm volatile("cp.async.cg.shared.global [%0], [%1], 16;\n" :: "r"(dst), "l"(src) : "memory");
}
#define CP_COMMIT() asm volatile("cp.async.commit_group;\n" ::: "memory")
#define CP_WAIT0()  asm volatile("cp.async.wait_group 0;\n" ::: "memory")

#define LDSM4(r, a) \
    asm volatile("ldmatrix.sync.aligned.m8n8.x4.shared.b16 {%0,%1,%2,%3}, [%4];" \
                 : "=r"((r)[0]), "=r"((r)[1]), "=r"((r)[2]), "=r"((r)[3]) : "r"(a))

#define MMA16816(d, a, b0, b1) \
    asm volatile("mma.sync.aligned.m16n8k16.row.col.f32.bf16.bf16.f32 " \
                 "{%0,%1,%2,%3}, {%4,%5,%6,%7}, {%8,%9}, {%0,%1,%2,%3};" \
                 : "+f"((d)[0]), "+f"((d)[1]), "+f"((d)[2]), "+f"((d)[3]) \
                 : "r"((a)[0]), "r"((a)[1]), "r"((a)[2]), "r"((a)[3]), \
                   "r"(b0), "r"(b1))

// ---------------------------------------------------------------------------
// Prep: centers fp32 -> bf16 + ||c||^2. One block per cluster row.
// ---------------------------------------------------------------------------
__global__ void prep_kernel(const float* __restrict__ centers) {
    const int c = blockIdx.x, t = threadIdx.x;       // 256 threads
    const float2* row = reinterpret_cast<const float2*>(centers + (size_t)c * DHID);
    float2 v = row[t];
    reinterpret_cast<uint32_t*>(g_wbf + (size_t)c * DHID)[t] = pack_bf16(v.x, v.y);
    float s = v.x * v.x + v.y * v.y;
    #pragma unroll
    for (int o = 16; o > 0; o >>= 1) s += __shfl_xor_sync(0xffffffffu, s, o);
    __shared__ float ws[8];
    if ((t & 31) == 0) ws[t >> 5] = s;
    __syncthreads();
    if (t == 0) {
        float tot = 0.f;
        #pragma unroll
        for (int i = 0; i < 8; i++) tot += ws[i];
        g_c2[c] = tot;
    }
}

// ---------------------------------------------------------------------------
// Main fused kernel: 64 rows x 512 clusters per CTA, 16 warps (64x32 per warp).
// ---------------------------------------------------------------------------
extern __shared__ char dynsmem[];

__global__ __launch_bounds__(NT, 1)
void qsoft_mma_kernel(const float* __restrict__ x, float* __restrict__ out) {
    __shared__ float xs_sm[BM];
    __shared__ float c2s[KC];
    __shared__ float rs_sm[BM][16];
    __shared__ float inv_sm[BM];

    const int tid  = threadIdx.x;
    const int wid  = tid >> 5;
    const int lane = tid & 31;
    const int rowBase = blockIdx.x * BM;

    const uint32_t sbase = (smem_u32(dynsmem) + 1023u) & ~1023u;
    const uint32_t Abuf[2] = { sbase,              sbase + A_STAGE };
    const uint32_t Bbuf[2] = { sbase + 2*A_STAGE,  sbase + 2*A_STAGE + B_STAGE };

    // A-load mapping: row = tid/8, 8 floats at col (tid%8)*8
    const int arow = tid >> 3;
    const int asub = tid & 7;

    float acc[4][4][4];
    #pragma unroll
    for (int mi = 0; mi < 4; mi++)
        #pragma unroll
        for (int ni = 0; ni < 4; ni++)
            #pragma unroll
            for (int e = 0; e < 4; e++) acc[mi][ni][e] = 0.f;

    float sq = 0.f;
    float4 f[2];

    // ldmatrix lane addressing (within-tile offsets)
    const int a_r  = ((lane >> 3) & 1) * 8 + (lane & 7);   // A row in m16
    const int a_kb = ((lane >> 4) & 1) * 16;               // A k-byte
    const int b_r  = ((lane >> 4) & 1) * 8 + (lane & 7);   // B row in n16
    const int b_kb = ((lane >> 3) & 1) * 16;               // B k-byte

    // ---------------- loaders ----------------
    auto lda = [&](int c) {
        const float4* src = reinterpret_cast<const float4*>(
            x + (size_t)(rowBase + arow) * DHID + c * BK + asub * 8);
        f[0] = src[0];
        f[1] = src[1];
    };
    auto sta = [&](int s) {
        #pragma unroll
        for (int i = 0; i < 2; i++)
            sq += f[i].x*f[i].x + f[i].y*f[i].y + f[i].z*f[i].z + f[i].w*f[i].w;
        uint32_t p0 = pack_bf16(f[0].x, f[0].y);
        uint32_t p1 = pack_bf16(f[0].z, f[0].w);
        uint32_t p2 = pack_bf16(f[1].x, f[1].y);
        uint32_t p3 = pack_bf16(f[1].z, f[1].w);
        uint32_t off = (uint32_t)arow * 128u + (uint32_t)asub * 16u;
        asm volatile("st.shared.v4.b32 [%0], {%1,%2,%3,%4};"
                     :: "r"(Abuf[s] + SWZ128(off)),
                        "r"(p0), "r"(p1), "r"(p2), "r"(p3) : "memory");
    };
    auto ldb = [&](int c, int s) {
        #pragma unroll
        for (int k = 0; k < 8; k++) {
            int idx = tid + k * NT;          // 0..4095 (16B chunks)
            int n = idx >> 3, i = idx & 7;
            const char* src = reinterpret_cast<const char*>(g_wbf)
                            + (size_t)n * (DHID * 2) + c * 128 + i * 16;
            uint32_t off = (uint32_t)n * 128u + (uint32_t)i * 16u;
            cp_async16(Bbuf[s] + SWZ128(off), src);
        }
    };

    // ---------------- compute one K-chunk (warp: 64 rows x 32 cols) ----------
    auto compute = [&](int s) {
        const uint32_t Ab = Abuf[s], Bb = Bbuf[s];
        #pragma unroll
        for (int ks = 0; ks < 4; ks++) {
            uint32_t b[2][4];
            #pragma unroll
            for (int j = 0; j < 2; j++) {
                uint32_t off = (uint32_t)(wid * 32 + j * 16 + b_r) * 128u
                             + (uint32_t)(ks * 32 + b_kb);
                LDSM4(b[j], Bb + SWZ128(off));
            }
            #pragma unroll
            for (int mi = 0; mi < 4; mi++) {
                uint32_t a[4];
                uint32_t off = (uint32_t)(mi * 16 + a_r) * 128u
                             + (uint32_t)(ks * 32 + a_kb);
                LDSM4(a, Ab + SWZ128(off));
                #pragma unroll
                for (int j = 0; j < 2; j++) {
                    MMA16816(acc[mi][2*j],   a, b[j][0], b[j][1]);
                    MMA16816(acc[mi][2*j+1], a, b[j][2], b[j][3]);
                }
            }
        }
    };

    // ---------------- pipeline ----------------
    lda(0);
    ldb(0, 0); CP_COMMIT();
    sta(0);
    CP_WAIT0(); __syncthreads();

    for (int c = 0; c < NCH; c++) {
        const int s = c & 1;
        if (c + 1 < NCH) { lda(c + 1); ldb(c + 1, s ^ 1); CP_COMMIT(); }
        compute(s);
        if (c + 1 < NCH) { sta(s ^ 1); CP_WAIT0(); }
        __syncthreads();
    }

    // ---------------- epilogue ----------------
    // ||x||^2: row owned by 8 consecutive lanes -> xor 1,2,4
    sq += __shfl_xor_sync(0xffffffffu, sq, 1);
    sq += __shfl_xor_sync(0xffffffffu, sq, 2);
    sq += __shfl_xor_sync(0xffffffffu, sq, 4);
    if ((tid & 7) == 0) xs_sm[arow] = sq;
    for (int i = tid; i < KC; i += NT) c2s[i] = g_c2[i];
    __syncthreads();

    const int qrow = lane >> 2;            // 0..7
    const int wcol = wid * 32 + (lane & 3) * 2;

    float rsum[8];
    #pragma unroll
    for (int i = 0; i < 8; i++) rsum[i] = 0.f;

    #pragma unroll
    for (int mi = 0; mi < 4; mi++) {
        const float x20 = xs_sm[mi * 16 + qrow];
        const float x21 = xs_sm[mi * 16 + qrow + 8];
        #pragma unroll
        for (int ni = 0; ni < 4; ni++) {
            const float cc0 = c2s[wcol + ni * 8];
            const float cc1 = c2s[wcol + ni * 8 + 1];
            float q0 = __fdividef(1.f, 1.f + fmaxf(fmaf(-2.f, acc[mi][ni][0], x20 + cc0), 0.f));
            float q1 = __fdividef(1.f, 1.f + fmaxf(fmaf(-2.f, acc[mi][ni][1], x20 + cc1), 0.f));
            float q2 = __fdividef(1.f, 1.f + fmaxf(fmaf(-2.f, acc[mi][ni][2], x21 + cc0), 0.f));
            float q3 = __fdividef(1.f, 1.f + fmaxf(fmaf(-2.f, acc[mi][ni][3], x21 + cc1), 0.f));
            acc[mi][ni][0] = q0; acc[mi][ni][1] = q1;
            acc[mi][ni][2] = q2; acc[mi][ni][3] = q3;
            rsum[2*mi]   += q0 + q1;
            rsum[2*mi+1] += q2 + q3;
        }
    }
    #pragma unroll
    for (int i = 0; i < 8; i++) {
        float v = rsum[i];
        v += __shfl_xor_sync(0xffffffffu, v, 1);
        v += __shfl_xor_sync(0xffffffffu, v, 2);
        rsum[i] = v;
    }
    if ((lane & 3) == 0) {
        #pragma unroll
        for (int mi = 0; mi < 4; mi++) {
            rs_sm[mi * 16 + qrow][wid]     = rsum[2*mi];
            rs_sm[mi * 16 + qrow + 8][wid] = rsum[2*mi+1];
        }
    }
    __syncthreads();
    if (tid < BM) {
        float t = 0.f;
        #pragma unroll
        for (int w = 0; w < 16; w++) t += rs_sm[tid][w];
        inv_sm[tid] = __fdividef(1.f, t);
    }
    __syncthreads();

    #pragma unroll
    for (int mi = 0; mi < 4; mi++) {
        const int r0 = mi * 16 + qrow, r1 = r0 + 8;
        const float inv0 = inv_sm[r0], inv1 = inv_sm[r1];
        float* o0 = out + (size_t)(rowBase + r0) * KC + wcol;
        float* o1 = out + (size_t)(rowBase + r1) * KC + wcol;
        #pragma unroll
        for (int ni = 0; ni < 4; ni++) {
            *reinterpret_cast<float2*>(o0 + ni * 8) =
                make_float2(acc[mi][ni][0] * inv0, acc[mi][ni][1] * inv0);
            *reinterpret_cast<float2*>(o1 + ni * 8) =
                make_float2(acc[mi][ni][2] * inv1, acc[mi][ni][3] * inv1);
        }
    }
}

// ---------------------------------------------------------------------------
extern "C" void kernel_launch(void* const* d_in, const int* in_sizes, int n_in,
                              void* d_out, int out_size) {
    const float* x       = (const float*)d_in[0];
    const float* centers = (const float*)d_in[1];
    float*       out     = (float*)d_out;
    const int N = in_sizes[0] / DHID;   // 131072

    cudaFuncSetAttribute(qsoft_mma_kernel,
                         cudaFuncAttributeMaxDynamicSharedMemorySize, DYN_SMEM);

    prep_kernel<<<KC, 256>>>(centers);
    qsoft_mma_kernel<<<N / BM, NT, DYN_SMEM>>>(x, out);
}